// round 1
// baseline (speedup 1.0000x reference)
#include <cuda_runtime.h>
#include <cstdint>

#define BB 4096
#define LL 16
#define DD 512
#define CJ 128                 // j's per chunk (one block stages one chunk)
#define NCHUNK (BB / CJ)       // 32
#define NIG (BB / 256)         // 16 i-groups of 256

#define LOG2E_F   1.4426950408889634f
#define LN2_F     0.6931471805599453f
#define LOG_2PI_F 1.8378770664093453f
#define NEG_INF_F (__int_as_float(0xff800000))

// ---- scratch (no allocations allowed) ----
__device__ float g_coef[BB * 48];                 // per j: c0[16], c1[16], c2[16] (log2 domain, max-folded)
__device__ float g_M[32];                         // M_l for l=0..15, g_M[16] = sum_l M_l
__device__ float g_part[(size_t)NCHUNK * 17 * BB];// per chunk, per accumulator, per i: partial sum of exps
__device__ float g_tcpart[NIG];                   // per-block (tc_i + kl_i) sums
__device__ float g_reconpart[256];                // per-block |data-recon| sums

__device__ __forceinline__ float ex2f(float x) {
    float y; asm("ex2.approx.ftz.f32 %0, %1;" : "=f"(y) : "f"(x)); return y;
}
__device__ __forceinline__ float lg2f(float x) {
    float y; asm("lg2.approx.f32 %0, %1;" : "=f"(y) : "f"(x)); return y;
}

// ---------------------------------------------------------------------------
// Kernel 1: M_l = max_j b2(j,l),  b2 = -0.5*log2e*(lv + log(2pi)). Exact max,
// order-independent -> deterministic.
// ---------------------------------------------------------------------------
__global__ void k_max(const float* __restrict__ lv) {
    __shared__ float sm[256 * 16];
    __shared__ float sM[16];
    float lm[16];
#pragma unroll
    for (int l = 0; l < 16; l++) lm[l] = NEG_INF_F;
    for (int j = threadIdx.x; j < BB; j += 256) {
#pragma unroll
        for (int l = 0; l < 16; l++) {
            float v  = lv[j * 16 + l];
            float b2 = -0.5f * LOG2E_F * (v + LOG_2PI_F);
            lm[l] = fmaxf(lm[l], b2);
        }
    }
#pragma unroll
    for (int l = 0; l < 16; l++) sm[threadIdx.x * 16 + l] = lm[l];
    __syncthreads();
    if (threadIdx.x < 16) {
        float m = NEG_INF_F;
        for (int t = 0; t < 256; t++) m = fmaxf(m, sm[t * 16 + threadIdx.x]);
        sM[threadIdx.x] = m;
    }
    __syncthreads();
    if (threadIdx.x == 0) {
        float s = 0.f;
        for (int l = 0; l < 16; l++) { g_M[l] = sM[l]; s += sM[l]; }
        g_M[16] = s;
    }
}

// ---------------------------------------------------------------------------
// Kernel 2: coefficients per j (row of z_mean / z_log_var):
//   p2(i,j,l) = c2*z^2 + c1*z + c0   (log2 domain, c0 already minus M_l)
// ---------------------------------------------------------------------------
__global__ void k_coef(const float* __restrict__ zm, const float* __restrict__ lv) {
    int j = blockIdx.x * 256 + threadIdx.x;
#pragma unroll
    for (int l = 0; l < 16; l++) {
        float m  = zm[j * 16 + l];
        float v  = lv[j * 16 + l];
        float a2 = -0.5f * LOG2E_F * __expf(-v);
        float b2 = -0.5f * LOG2E_F * (v + LOG_2PI_F);
        float c0 = fmaf(a2, m * m, b2) - g_M[l];
        float c1 = -2.0f * a2 * m;
        g_coef[j * 48 + l]      = c0;
        g_coef[j * 48 + 16 + l] = c1;
        g_coef[j * 48 + 32 + l] = a2;
    }
}

// ---------------------------------------------------------------------------
// Kernel 3 (hot loop): each lane owns one i; block stages one 128-j coefficient
// chunk in smem (warp-uniform broadcast reads). For each j: 16 per-latent
// exponents (all <= 0) + their sum; accumulate plain sums of exp2.
// ---------------------------------------------------------------------------
__global__ void __launch_bounds__(256, 2) k_main(const float* __restrict__ z) {
    __shared__ float4 smc[CJ * 12];                 // 48 floats per j
    const int ig = blockIdx.x, ch = blockIdx.y;
    const int tid = threadIdx.x;

    // stage coefficient chunk (coalesced float4)
    const float4* gc = (const float4*)(g_coef + (size_t)ch * CJ * 48);
    for (int k = tid; k < CJ * 12; k += 256) smc[k] = gc[k];

    // this thread's i-row of z
    const int i = ig * 256 + tid;
    float zr[16], z2r[16];
    const float4* zp = (const float4*)(z + (size_t)i * 16);
#pragma unroll
    for (int q = 0; q < 4; q++) {
        float4 t = zp[q];
        zr[4*q+0] = t.x; zr[4*q+1] = t.y; zr[4*q+2] = t.z; zr[4*q+3] = t.w;
    }
#pragma unroll
    for (int l = 0; l < 16; l++) z2r[l] = zr[l] * zr[l];

    float s[17];
#pragma unroll
    for (int a = 0; a < 17; a++) s[a] = 0.f;

    __syncthreads();

    for (int jj = 0; jj < CJ; jj++) {
        const float4* C = &smc[jj * 12];
        float v[16];
#pragma unroll
        for (int g = 0; g < 4; g++) {
            float4 c0 = C[g], c1 = C[4 + g], c2 = C[8 + g];
            v[4*g+0] = fmaf(c2.x, z2r[4*g+0], fmaf(c1.x, zr[4*g+0], c0.x));
            v[4*g+1] = fmaf(c2.y, z2r[4*g+1], fmaf(c1.y, zr[4*g+1], c0.y));
            v[4*g+2] = fmaf(c2.z, z2r[4*g+2], fmaf(c1.z, zr[4*g+2], c0.z));
            v[4*g+3] = fmaf(c2.w, z2r[4*g+3], fmaf(c1.w, zr[4*g+3], c0.w));
        }
        // tree-sum of the 16 exponents (== ps - sum_l M_l, guaranteed <= 0)
        float p0 = (v[0] + v[1]) + (v[2]  + v[3]);
        float p1 = (v[4] + v[5]) + (v[6]  + v[7]);
        float p2 = (v[8] + v[9]) + (v[10] + v[11]);
        float p3 = (v[12]+ v[13])+ (v[14] + v[15]);
        float ps = (p0 + p1) + (p2 + p3);
#pragma unroll
        for (int l = 0; l < 16; l++) s[l] += ex2f(v[l]);
        s[16] += ex2f(ps);
    }

    // coalesced partial writes: [chunk][acc][i]
    float* gp = g_part + (size_t)ch * 17 * BB;
#pragma unroll
    for (int a = 0; a < 17; a++) gp[(size_t)a * BB + i] = s[a];
}

// ---------------------------------------------------------------------------
// Kernel 4: per-i merge of chunk partials (exact adds -> deterministic),
// convert to natural-log LSEs, add KL term, block-sum.
// ---------------------------------------------------------------------------
__global__ void k_reduce(const float* __restrict__ zm, const float* __restrict__ lv) {
    const int i = blockIdx.x * 256 + threadIdx.x;
    float acc[17];
#pragma unroll
    for (int a = 0; a < 17; a++) acc[a] = 0.f;
    for (int c = 0; c < NCHUNK; c++) {
        const float* gp = g_part + (size_t)c * 17 * BB;
#pragma unroll
        for (int a = 0; a < 17; a++) acc[a] += gp[(size_t)a * BB + i];
    }
    float lse[17];
#pragma unroll
    for (int a = 0; a < 17; a++) lse[a] = (g_M[a] + lg2f(acc[a])) * LN2_F;

    float prod = 0.f;
#pragma unroll
    for (int l = 0; l < 16; l++) prod += lse[l];
    float tc = lse[16] - prod;

    float kl = 0.f;
#pragma unroll
    for (int l = 0; l < 16; l++) {
        float m = zm[i * 16 + l], v = lv[i * 16 + l];
        kl += fmaf(m, m, __expf(v)) - v - 1.0f;
    }
    float val = tc + 0.5f * kl;

    __shared__ float sm[256];
    sm[threadIdx.x] = val;
    __syncthreads();
    for (int st = 128; st > 0; st >>= 1) {
        if (threadIdx.x < st) sm[threadIdx.x] += sm[threadIdx.x + st];
        __syncthreads();
    }
    if (threadIdx.x == 0) g_tcpart[blockIdx.x] = sm[0];
}

// ---------------------------------------------------------------------------
// Kernel 5: reconstruction MAE partial sums (fixed grid-stride assignment).
// ---------------------------------------------------------------------------
__global__ void k_recon(const float* __restrict__ a, const float* __restrict__ b) {
    int tid = blockIdx.x * 256 + threadIdx.x;
    float acc = 0.f;
    for (int k = tid; k < BB * DD; k += 256 * 256) acc += fabsf(a[k] - b[k]);
    __shared__ float sm[256];
    sm[threadIdx.x] = acc;
    __syncthreads();
    for (int st = 128; st > 0; st >>= 1) {
        if (threadIdx.x < st) sm[threadIdx.x] += sm[threadIdx.x + st];
        __syncthreads();
    }
    if (threadIdx.x == 0) g_reconpart[blockIdx.x] = sm[0];
}

// ---------------------------------------------------------------------------
// Kernel 6: final deterministic combine -> scalar.
// ---------------------------------------------------------------------------
__global__ void k_final(float* __restrict__ out) {
    __shared__ float sm[256];
    sm[threadIdx.x] = g_reconpart[threadIdx.x];
    __syncthreads();
    for (int st = 128; st > 0; st >>= 1) {
        if (threadIdx.x < st) sm[threadIdx.x] += sm[threadIdx.x + st];
        __syncthreads();
    }
    float recon = sm[0] / (float)(BB * DD);
    __syncthreads();
    sm[threadIdx.x] = (threadIdx.x < NIG) ? g_tcpart[threadIdx.x] : 0.f;
    __syncthreads();
    for (int st = 128; st > 0; st >>= 1) {
        if (threadIdx.x < st) sm[threadIdx.x] += sm[threadIdx.x + st];
        __syncthreads();
    }
    if (threadIdx.x == 0) out[0] = recon + sm[0] / (float)BB;
}

extern "C" void kernel_launch(void* const* d_in, const int* in_sizes, int n_in,
                              void* d_out, int out_size) {
    const float* data = (const float*)d_in[0];
    const float* rec  = (const float*)d_in[1];
    const float* z    = (const float*)d_in[2];
    const float* zm   = (const float*)d_in[3];
    const float* lv   = (const float*)d_in[4];
    float* out = (float*)d_out;

    k_max  <<<1,   256>>>(lv);
    k_coef <<<BB/256, 256>>>(zm, lv);
    k_recon<<<256, 256>>>(data, rec);
    dim3 g(NIG, NCHUNK);
    k_main <<<g,   256>>>(z);
    k_reduce<<<NIG, 256>>>(zm, lv);
    k_final<<<1,   256>>>(out);
}

// round 2
// speedup vs baseline: 1.3524x; 1.3524x over previous
#include <cuda_runtime.h>
#include <cstdint>

#define BB 4096
#define LL 16
#define DD 512
#define CJ 128                 // j's per chunk (one block stages one chunk)
#define NCHUNK (BB / CJ)       // 32
#define NIG (BB / 256)         // 16 i-groups of 256
#define NJB (BB / 256)         // 16 j-blocks in k_coef

#define LOG2E_F   1.4426950408889634f
#define LN2_F     0.6931471805599453f
#define LOG_2PI_F 1.8378770664093453f
#define NEG_INF_F (__int_as_float(0xff800000))

typedef unsigned long long ull;

// ---- scratch (no allocations allowed) ----
__device__ float g_coef[BB * 48];                  // per j: c0[16](no M), c1[16], c2[16] (log2 domain)
__device__ float g_Mp[NJB * 16];                   // per-block per-l partial max of b2
__device__ float g_part[(size_t)NCHUNK * 17 * BB]; // per chunk, per accumulator, per i
__device__ float g_tcpart[NIG];                    // per-block (tc_i + 0.5*kl_i) sums
__device__ float g_reconpart[512];                 // per-k_main-block |data-recon| sums

__device__ __forceinline__ float ex2f(float x) {
    float y; asm("ex2.approx.ftz.f32 %0, %1;" : "=f"(y) : "f"(x)); return y;
}
__device__ __forceinline__ float lg2f(float x) {
    float y; asm("lg2.approx.f32 %0, %1;" : "=f"(y) : "f"(x)); return y;
}
// packed f32x2 ops (Blackwell): 2 fp32 lanes per issue on the fma pipe
__device__ __forceinline__ ull fma2(ull a, ull b, ull c) {
    ull d; asm("fma.rn.f32x2 %0, %1, %2, %3;" : "=l"(d) : "l"(a), "l"(b), "l"(c)); return d;
}
__device__ __forceinline__ ull add2(ull a, ull b) {
    ull d; asm("add.rn.f32x2 %0, %1, %2;" : "=l"(d) : "l"(a), "l"(b)); return d;
}
__device__ __forceinline__ ull mul2(ull a, ull b) {
    ull d; asm("mul.rn.f32x2 %0, %1, %2;" : "=l"(d) : "l"(a), "l"(b)); return d;
}
__device__ __forceinline__ ull pack2(float lo, float hi) {
    ull d; asm("mov.b64 %0, {%1, %2};" : "=l"(d) : "f"(lo), "f"(hi)); return d;
}
__device__ __forceinline__ void unpack2(ull v, float& lo, float& hi) {
    asm("mov.b64 {%0, %1}, %2;" : "=f"(lo), "=f"(hi) : "l"(v));
}

// ---------------------------------------------------------------------------
// K1: per-j coefficients (log2 domain, NO max folded) + per-block per-l max
// partials of b2.  p2(i,j,l) = c2*z^2 + c1*z + c0;  max_z p2 = b2 = c0 @vertex.
// ---------------------------------------------------------------------------
__global__ void k_coef(const float* __restrict__ zm, const float* __restrict__ lv) {
    const int tid = threadIdx.x;
    const int j = blockIdx.x * 256 + tid;
    float b2v[16];
#pragma unroll
    for (int l = 0; l < 16; l++) {
        float m  = zm[j * 16 + l];
        float v  = lv[j * 16 + l];
        float a2 = -0.5f * LOG2E_F * __expf(-v);
        float b2 = -0.5f * LOG2E_F * (v + LOG_2PI_F);
        float c0 = fmaf(a2, m * m, b2);          // value at z=0; note p2 = a2*(z-m)^2 + b2
        float c1 = -2.0f * a2 * m;
        g_coef[j * 48 + l]      = c0;
        g_coef[j * 48 + 16 + l] = c1;
        g_coef[j * 48 + 32 + l] = a2;
        b2v[l] = b2;
    }
    // block max per l (exact max => order-independent => deterministic)
    __shared__ float sred[8][16];
    const int wid = tid >> 5;
#pragma unroll
    for (int l = 0; l < 16; l++) {
        float v = b2v[l];
        for (int off = 16; off > 0; off >>= 1)
            v = fmaxf(v, __shfl_xor_sync(0xffffffffu, v, off));
        if ((tid & 31) == 0) sred[wid][l] = v;
    }
    __syncthreads();
    if (tid < 16) {
        float m = NEG_INF_F;
        for (int w = 0; w < 8; w++) m = fmaxf(m, sred[w][tid]);
        g_Mp[blockIdx.x * 16 + tid] = m;
    }
}

// ---------------------------------------------------------------------------
// K2 (hot): lane = i, loop = j over a 128-j smem-staged coefficient chunk.
// M_l folded into c0 at staging. 16 FFMA2 + exps per j; exp2(sum) computed as
// product of per-latent exps (saves 1 MUFU/pair). Recon MAE slice fused in.
// ---------------------------------------------------------------------------
__global__ void __launch_bounds__(256, 2) k_main(const float* __restrict__ z,
                                                 const float* __restrict__ data,
                                                 const float* __restrict__ rec) {
    __shared__ float4 smc[CJ * 12];
    __shared__ float sM[16];
    __shared__ float sredr[256];
    const int ig = blockIdx.x, ch = blockIdx.y;
    const int tid = threadIdx.x;

    // reduce M_l over coef-block partials (redundant per block; cheap; exact)
    if (tid < 16) {
        float m = NEG_INF_F;
#pragma unroll
        for (int b = 0; b < NJB; b++) m = fmaxf(m, g_Mp[b * 16 + tid]);
        sM[tid] = m;
    }
    __syncthreads();

    // stage coefficient chunk, folding -M_l into c0 vectors
    const float4* gc = (const float4*)(g_coef + (size_t)ch * CJ * 48);
    for (int k = tid; k < CJ * 12; k += 256) {
        float4 t = gc[k];
        int r = k % 12;
        if (r < 4) {
            int lb = r * 4;
            t.x -= sM[lb]; t.y -= sM[lb + 1]; t.z -= sM[lb + 2]; t.w -= sM[lb + 3];
        }
        smc[k] = t;
    }

    // fused recon MAE slice: 4096 contiguous floats per block (fixed mapping)
    const int blin = ch * NIG + ig;   // 0..511
    float racc = 0.f;
    {
        const float4* da = (const float4*)(data + (size_t)blin * 4096);
        const float4* rb = (const float4*)(rec  + (size_t)blin * 4096);
#pragma unroll
        for (int q = 0; q < 4; q++) {
            float4 a = da[tid + q * 256], b = rb[tid + q * 256];
            racc += (fabsf(a.x - b.x) + fabsf(a.y - b.y)) + (fabsf(a.z - b.z) + fabsf(a.w - b.w));
        }
    }
    sredr[tid] = racc;
    __syncthreads();   // also publishes smc
    for (int st = 128; st > 0; st >>= 1) {
        if (tid < st) sredr[tid] += sredr[tid + st];
        __syncthreads();
    }
    if (tid == 0) g_reconpart[blin] = sredr[0];

    // this thread's i-row of z, packed into f32x2 pairs
    const int i = ig * 256 + tid;
    ull zz[8], z2[8];
    {
        const float4* zp = (const float4*)(z + (size_t)i * 16);
#pragma unroll
        for (int q = 0; q < 4; q++) {
            float4 t = zp[q];
            zz[2*q]   = pack2(t.x, t.y);
            zz[2*q+1] = pack2(t.z, t.w);
        }
#pragma unroll
        for (int g = 0; g < 8; g++) z2[g] = mul2(zz[g], zz[g]);
    }

    ull s[8];
#pragma unroll
    for (int g = 0; g < 8; g++) s[g] = 0ull;
    float s16 = 0.f;

    const ulonglong2* Cb = (const ulonglong2*)smc;
    for (int jj = 0; jj < CJ; jj++) {
        const ulonglong2* C = Cb + jj * 6;  // 6 x ulonglong2 = 12 pairs? no: 12 float4 = 6 ulonglong2*2
        // layout per j: 12 float4 = 24 ull pairs; as ulonglong2: 12 entries
        const ulonglong2* C0 = (const ulonglong2*)(smc + jj * 12);
        ull e[8];
#pragma unroll
        for (int h = 0; h < 4; h++) {
            ulonglong2 c0 = C0[h];          // c0 pairs 2h, 2h+1
            ulonglong2 c1 = C0[4 + h];
            ulonglong2 c2 = C0[8 + h];
            ull va = fma2(c2.x, z2[2*h],   fma2(c1.x, zz[2*h],   c0.x));
            ull vb = fma2(c2.y, z2[2*h+1], fma2(c1.y, zz[2*h+1], c0.y));
            float al, ah, bl, bh;
            unpack2(va, al, ah); unpack2(vb, bl, bh);
            e[2*h]   = pack2(ex2f(al), ex2f(ah));
            e[2*h+1] = pack2(ex2f(bl), ex2f(bh));
            s[2*h]   = add2(s[2*h],   e[2*h]);
            s[2*h+1] = add2(s[2*h+1], e[2*h+1]);
        }
        // exp2(sum_l v_l) = product of the 16 per-latent exps (packed tree)
        ull m0 = mul2(e[0], e[1]), m1 = mul2(e[2], e[3]);
        ull m2 = mul2(e[4], e[5]), m3 = mul2(e[6], e[7]);
        ull mm0 = mul2(m0, m1), mm1 = mul2(m2, m3);
        ull mmm = mul2(mm0, mm1);
        float pa, pb; unpack2(mmm, pa, pb);
        s16 += pa * pb;
    }
    (void)Cb;

    // coalesced partial writes: [chunk][acc][i]
    float* gp = g_part + (size_t)ch * 17 * BB;
#pragma unroll
    for (int g = 0; g < 8; g++) {
        float lo, hi; unpack2(s[g], lo, hi);
        gp[(size_t)(2*g)   * BB + i] = lo;
        gp[(size_t)(2*g+1) * BB + i] = hi;
    }
    gp[(size_t)16 * BB + i] = s16;
}

// ---------------------------------------------------------------------------
// K3: per-i merge of chunk partials (fixed order), LSEs, KL, block-sum.
// ---------------------------------------------------------------------------
__global__ void k_reduce(const float* __restrict__ zm, const float* __restrict__ lv) {
    __shared__ float sM[16];
    const int tid = threadIdx.x;
    const int i = blockIdx.x * 256 + tid;
    if (tid < 16) {
        float m = NEG_INF_F;
#pragma unroll
        for (int b = 0; b < NJB; b++) m = fmaxf(m, g_Mp[b * 16 + tid]);
        sM[tid] = m;
    }
    __syncthreads();
    float msum = 0.f;
#pragma unroll
    for (int l = 0; l < 16; l++) msum += sM[l];

    float acc[17];
#pragma unroll
    for (int a = 0; a < 17; a++) acc[a] = 0.f;
    for (int c = 0; c < NCHUNK; c++) {
        const float* gp = g_part + (size_t)c * 17 * BB;
#pragma unroll
        for (int a = 0; a < 17; a++) acc[a] += gp[(size_t)a * BB + i];
    }
    float prod = 0.f;
#pragma unroll
    for (int l = 0; l < 16; l++) prod += (sM[l] + lg2f(acc[l])) * LN2_F;
    float tc = (msum + lg2f(acc[16])) * LN2_F - prod;

    float kl = 0.f;
#pragma unroll
    for (int l = 0; l < 16; l++) {
        float m = zm[i * 16 + l], v = lv[i * 16 + l];
        kl += fmaf(m, m, __expf(v)) - v - 1.0f;
    }
    float val = tc + 0.5f * kl;

    __shared__ float sm[256];
    sm[tid] = val;
    __syncthreads();
    for (int st = 128; st > 0; st >>= 1) {
        if (tid < st) sm[tid] += sm[tid + st];
        __syncthreads();
    }
    if (tid == 0) g_tcpart[blockIdx.x] = sm[0];
}

// ---------------------------------------------------------------------------
// K4: final deterministic combine -> scalar.
// ---------------------------------------------------------------------------
__global__ void k_final(float* __restrict__ out) {
    __shared__ float sm[512];
    __shared__ float sRecon;
    const int tid = threadIdx.x;
    sm[tid] = g_reconpart[tid];
    __syncthreads();
    for (int st = 256; st > 0; st >>= 1) {
        if (tid < st) sm[tid] += sm[tid + st];
        __syncthreads();
    }
    if (tid == 0) sRecon = sm[0];
    __syncthreads();
    sm[tid] = (tid < NIG) ? g_tcpart[tid] : 0.f;
    __syncthreads();
    for (int st = 256; st > 0; st >>= 1) {
        if (tid < st) sm[tid] += sm[tid + st];
        __syncthreads();
    }
    if (tid == 0) out[0] = sRecon / (float)(BB * DD) + sm[0] / (float)BB;
}

extern "C" void kernel_launch(void* const* d_in, const int* in_sizes, int n_in,
                              void* d_out, int out_size) {
    const float* data = (const float*)d_in[0];
    const float* rec  = (const float*)d_in[1];
    const float* z    = (const float*)d_in[2];
    const float* zm   = (const float*)d_in[3];
    const float* lv   = (const float*)d_in[4];
    float* out = (float*)d_out;

    k_coef  <<<NJB, 256>>>(zm, lv);
    dim3 g(NIG, NCHUNK);
    k_main  <<<g, 256>>>(z, data, rec);
    k_reduce<<<NIG, 256>>>(zm, lv);
    k_final <<<1, 512>>>(out);
}